// round 13
// baseline (speedup 1.0000x reference)
#include <cuda_runtime.h>
#include <cuda_bf16.h>
#include <cuda_fp16.h>
#include <stdint.h>

// ---------------------------------------------------------------------------
// Problem dims
// ---------------------------------------------------------------------------
static const int cNS  = 8192;
static const int cNK  = 8192;
static const int cHID = 1024;
static const int cKED = 2048;
static const int CHUNKS = 64;  // softmax row chunks = one 128-row CTA tile each

// ---------------------------------------------------------------------------
// Scratch (__device__ globals; allocation-free)
// ---------------------------------------------------------------------------
__device__ __nv_bfloat16 g_Xs_h[(size_t)cNS * cHID];
__device__ __nv_bfloat16 g_Xs_l[(size_t)cNS * cHID];
__device__ __nv_bfloat16 g_Xk_h[(size_t)cNK * cKED];
__device__ __nv_bfloat16 g_Xk_l[(size_t)cNK * cKED];
__device__ __nv_bfloat16 g_Ws_h[(size_t)cHID * cHID];
__device__ __nv_bfloat16 g_Ws_l[(size_t)cHID * cHID];
__device__ __nv_bfloat16 g_Wk_h[(size_t)cHID * cKED];
__device__ __nv_bfloat16 g_Wk_l[(size_t)cHID * cKED];
__device__ __nv_bfloat16 g_S_h[(size_t)cNS * cHID];
__device__ __nv_bfloat16 g_S_l[(size_t)cNS * cHID];
__device__ __nv_bfloat16 g_K_h[(size_t)cNK * cHID];
__device__ __nv_bfloat16 g_K_l[(size_t)cNK * cHID];
__device__ __half g_VT[(size_t)cKED * cNK];            // V^T fp16 [2048, 8192]
__device__ float g_Sc[(size_t)cNS * cNK];              // raw fp32 scores scratch
__device__ float g_pm[(size_t)CHUNKS * cNK];
__device__ float g_ps[(size_t)CHUNKS * cNK];
__device__ float g_m[cNK];
__device__ float g_rs[cNK];

// ---------------------------------------------------------------------------
// Helpers
// ---------------------------------------------------------------------------
__device__ __forceinline__ uint32_t smem_to_u32(const void* p) {
    uint32_t a;
    asm("{ .reg .u64 t; cvta.to.shared.u64 t, %1; cvt.u32.u64 %0, t; }"
        : "=r"(a) : "l"(p));
    return a;
}

__device__ __forceinline__ void cp_async16(uint32_t smem_addr, const void* gptr) {
    asm volatile("cp.async.cg.shared.global [%0], [%1], 16;\n"
                 :: "r"(smem_addr), "l"(__cvta_generic_to_global(gptr)));
}
__device__ __forceinline__ void cp_commit() {
    asm volatile("cp.async.commit_group;\n" ::: "memory");
}
template <int N>
__device__ __forceinline__ void cp_wait() {
    asm volatile("cp.async.wait_group %0;\n" :: "n"(N) : "memory");
}

__device__ __forceinline__ void ldsm_x4(uint32_t (&r)[4], uint32_t addr) {
    asm volatile("ldmatrix.sync.aligned.m8n8.x4.shared.b16 {%0,%1,%2,%3}, [%4];\n"
                 : "=r"(r[0]), "=r"(r[1]), "=r"(r[2]), "=r"(r[3]) : "r"(addr));
}

__device__ __forceinline__ void mma16816(float (&c)[4], const uint32_t (&a)[4],
                                         uint32_t b0, uint32_t b1) {
    asm volatile(
        "mma.sync.aligned.m16n8k16.row.col.f32.bf16.bf16.f32 "
        "{%0,%1,%2,%3}, {%4,%5,%6,%7}, {%8,%9}, {%0,%1,%2,%3};\n"
        : "+f"(c[0]), "+f"(c[1]), "+f"(c[2]), "+f"(c[3])
        : "r"(a[0]), "r"(a[1]), "r"(a[2]), "r"(a[3]), "r"(b0), "r"(b1));
}

__device__ __forceinline__ void mma16816h(float (&c)[4], const uint32_t (&a)[4],
                                          uint32_t b0, uint32_t b1) {
    asm volatile(
        "mma.sync.aligned.m16n8k16.row.col.f32.f16.f16.f32 "
        "{%0,%1,%2,%3}, {%4,%5,%6,%7}, {%8,%9}, {%0,%1,%2,%3};\n"
        : "+f"(c[0]), "+f"(c[1]), "+f"(c[2]), "+f"(c[3])
        : "r"(a[0]), "r"(a[1]), "r"(a[2]), "r"(a[3]), "r"(b0), "r"(b1));
}

__device__ __forceinline__ void split1(float x, __nv_bfloat16& h, __nv_bfloat16& l) {
    h = __float2bfloat16(x);
    l = __float2bfloat16(x - __bfloat162float(h));
}

// ---------------------------------------------------------------------------
// Split / fused split+transpose preprocessing
// ---------------------------------------------------------------------------
__global__ void split_kernel(const float* __restrict__ in,
                             __nv_bfloat16* __restrict__ hi,
                             __nv_bfloat16* __restrict__ lo, size_t n) {
    size_t i = ((size_t)blockIdx.x * 256 + threadIdx.x) * 4;
    if (i >= n) return;
    float4 v = *(const float4*)(in + i);
    __nv_bfloat16 h0, h1, h2, h3, l0, l1, l2, l3;
    split1(v.x, h0, l0); split1(v.y, h1, l1);
    split1(v.z, h2, l2); split1(v.w, h3, l3);
    *(__nv_bfloat162*)(hi + i)     = __nv_bfloat162(h0, h1);
    *(__nv_bfloat162*)(hi + i + 2) = __nv_bfloat162(h2, h3);
    *(__nv_bfloat162*)(lo + i)     = __nv_bfloat162(l0, l1);
    *(__nv_bfloat162*)(lo + i + 2) = __nv_bfloat162(l2, l3);
}

// Read Xk once: emit bf16 hi/lo planes (row-major) + fp16 V^T (transposed).
__global__ void split_transpose_kernel(const float* __restrict__ in,
                                       __nv_bfloat16* __restrict__ hi,
                                       __nv_bfloat16* __restrict__ lo,
                                       __half* __restrict__ vt,
                                       int R, int C) {
    __shared__ float t[32][33];
    int c0 = blockIdx.x * 32, r0 = blockIdx.y * 32;
    int tx = threadIdx.x, ty = threadIdx.y;
#pragma unroll
    for (int j = 0; j < 4; ++j) {
        float v = in[(size_t)(r0 + ty + j * 8) * C + c0 + tx];
        t[ty + j * 8][tx] = v;
        __nv_bfloat16 h, l; split1(v, h, l);
        size_t off = (size_t)(r0 + ty + j * 8) * C + c0 + tx;
        hi[off] = h; lo[off] = l;
    }
    __syncthreads();
#pragma unroll
    for (int j = 0; j < 4; ++j)
        vt[(size_t)(c0 + ty + j * 8) * R + r0 + tx] = __float2half(t[tx][ty + j * 8]);
}

// ---------------------------------------------------------------------------
// Common GEMM geometry: 128x128 CTA tile, BK=32, 3-stage cp.async pipeline,
// 8 warps (2x4), warp tile 64x32, 80B-padded SMEM rows (conflict-free ldsm).
// ---------------------------------------------------------------------------
static const int ROWB    = 80;                 // 64B data + 16B pad
static const int TILE_B  = 128 * ROWB;         // 10240 B per plane-tile

// === 3-pass split-bf16 GEMM: C = (Ah+Al) * (Bh+Bl)^T (+bias) ===
// STATS: also emit per-column chunk max/sumexp (softmax pass-1) from registers.
static const int STAGE_B3 = 4 * TILE_B;        // Ah, Al, Bh, Bl
static const int SMEM_3P  = 3 * STAGE_B3;      // 122880

template <bool BIAS, bool SPLIT, bool STATS>
__global__ __launch_bounds__(256, 1)
void mma_gemm(const __nv_bfloat16* __restrict__ Ah, const __nv_bfloat16* __restrict__ Al,
              const __nv_bfloat16* __restrict__ Bh, const __nv_bfloat16* __restrict__ Bl,
              const float* __restrict__ bias,
              float* __restrict__ C,
              __nv_bfloat16* __restrict__ Ch, __nv_bfloat16* __restrict__ Cl,
              int M, int N, int K)
{
    extern __shared__ char sm[];
    const uint32_t sbase = smem_to_u32(sm);

    const int tid = threadIdx.x;
    const int wid = tid >> 5, lane = tid & 31;
    const int wm = wid >> 2, wn = wid & 3;      // 2 x 4 warp grid
    const int row0 = blockIdx.y * 128, col0 = blockIdx.x * 128;

    const __nv_bfloat16* srcs[4] = {
        Ah + (size_t)row0 * K, Al + (size_t)row0 * K,
        Bh + (size_t)col0 * K, Bl + (size_t)col0 * K };

    const int NT = K >> 5;

    auto issue_loads = [&](int kt, int s) {
        const int k0 = kt << 5;
#pragma unroll
        for (int i = 0; i < 8; ++i) {
            int q = tid + i * 256;
            int t = q >> 9, idx = q & 511;
            int row = idx >> 2, c = idx & 3;
            const __nv_bfloat16* g = srcs[t] + (size_t)row * K + k0 + c * 8;
            uint32_t d = sbase + s * STAGE_B3 + t * TILE_B + row * ROWB + c * 16;
            cp_async16(d, g);
        }
    };

    issue_loads(0, 0); cp_commit();
    issue_loads(1, 1); cp_commit();

    float acc[4][4][4];
#pragma unroll
    for (int i = 0; i < 4; ++i)
#pragma unroll
        for (int j = 0; j < 4; ++j)
#pragma unroll
            for (int v = 0; v < 4; ++v) acc[i][j][v] = 0.f;

    const int lrow = lane & 15, lcol = lane >> 4;

    for (int kt = 0; kt < NT; ++kt) {
        const int s = kt % 3;
        cp_wait<1>();
        __syncthreads();
        if (kt + 2 < NT) issue_loads(kt + 2, (kt + 2) % 3);
        cp_commit();

#pragma unroll
        for (int ks = 0; ks < 2; ++ks) {
            uint32_t ah[4][4], al[4][4], bh[2][4], bl[2][4];
            const uint32_t abase = sbase + s * STAGE_B3
                + (wm * 64 + lrow) * ROWB + ks * 32 + lcol * 16;
#pragma unroll
            for (int mi = 0; mi < 4; ++mi) {
                ldsm_x4(ah[mi], abase + mi * 16 * ROWB);
                ldsm_x4(al[mi], abase + mi * 16 * ROWB + TILE_B);
            }
            const uint32_t bbase = sbase + s * STAGE_B3 + 2 * TILE_B
                + (wn * 32 + lrow) * ROWB + ks * 32 + lcol * 16;
#pragma unroll
            for (int bj = 0; bj < 2; ++bj) {
                ldsm_x4(bh[bj], bbase + bj * 16 * ROWB);
                ldsm_x4(bl[bj], bbase + bj * 16 * ROWB + TILE_B);
            }
#pragma unroll
            for (int mi = 0; mi < 4; ++mi) {
#pragma unroll
                for (int jn = 0; jn < 4; ++jn) {
                    const int bj = jn >> 1, hf = jn & 1;
                    mma16816(acc[mi][jn], ah[mi], bh[bj][hf], bh[bj][hf + 2]);
                    mma16816(acc[mi][jn], ah[mi], bl[bj][hf], bl[bj][hf + 2]);
                    mma16816(acc[mi][jn], al[mi], bh[bj][hf], bh[bj][hf + 2]);
                }
            }
        }
    }

    const int g = lane >> 2, cq = (lane & 3) * 2;
#pragma unroll
    for (int mi = 0; mi < 4; ++mi) {
#pragma unroll
        for (int jn = 0; jn < 4; ++jn) {
            const int r0w = row0 + wm * 64 + mi * 16 + g;
            const int cc = col0 + wn * 32 + jn * 8 + cq;
            float v0 = acc[mi][jn][0], v1 = acc[mi][jn][1];
            float v2 = acc[mi][jn][2], v3 = acc[mi][jn][3];
            if (BIAS) {
                float b0 = bias[cc], b1 = bias[cc + 1];
                v0 += b0; v1 += b1; v2 += b0; v3 += b1;
            }
            if (SPLIT) {
                __nv_bfloat16 h0, h1, h2, h3, l0, l1, l2, l3;
                split1(v0, h0, l0); split1(v1, h1, l1);
                split1(v2, h2, l2); split1(v3, h3, l3);
                size_t o0 = (size_t)r0w * N + cc;
                size_t o1 = (size_t)(r0w + 8) * N + cc;
                *(__nv_bfloat162*)(Ch + o0) = __nv_bfloat162(h0, h1);
                *(__nv_bfloat162*)(Cl + o0) = __nv_bfloat162(l0, l1);
                *(__nv_bfloat162*)(Ch + o1) = __nv_bfloat162(h2, h3);
                *(__nv_bfloat162*)(Cl + o1) = __nv_bfloat162(l2, l3);
            } else {
                *(float2*)(C + (size_t)r0w * N + cc)       = make_float2(v0, v1);
                *(float2*)(C + (size_t)(r0w + 8) * N + cc) = make_float2(v2, v3);
            }
        }
    }

    if (STATS) {
        // Softmax pass-1 from registers: per-column max / sumexp over this
        // CTA's 128 rows (chunk == blockIdx.y). Drain cp.async tail before
        // reusing stage smem (outstanding loads may target stage 0).
        cp_wait<0>();
        __syncthreads();
        float* SM_M = (float*)sm;            // [2][128]
        float* SM_S = (float*)(sm + 1024);   // [2][128]
#pragma unroll
        for (int jn = 0; jn < 4; ++jn) {
            float m0 = -1e30f, m1 = -1e30f;
#pragma unroll
            for (int mi = 0; mi < 4; ++mi) {
                m0 = fmaxf(m0, fmaxf(acc[mi][jn][0], acc[mi][jn][2]));
                m1 = fmaxf(m1, fmaxf(acc[mi][jn][1], acc[mi][jn][3]));
            }
            float s0 = 0.f, s1 = 0.f;
#pragma unroll
            for (int mi = 0; mi < 4; ++mi) {
                s0 += __expf(acc[mi][jn][0] - m0) + __expf(acc[mi][jn][2] - m0);
                s1 += __expf(acc[mi][jn][1] - m1) + __expf(acc[mi][jn][3] - m1);
            }
            // reduce across the 8 lanes (stride 4) sharing these two columns
#pragma unroll
            for (int o = 4; o < 32; o <<= 1) {
                float mo = __shfl_xor_sync(0xffffffffu, m0, o);
                float so = __shfl_xor_sync(0xffffffffu, s0, o);
                float nm = fmaxf(m0, mo);
                s0 = s0 * __expf(m0 - nm) + so * __expf(mo - nm); m0 = nm;
                mo = __shfl_xor_sync(0xffffffffu, m1, o);
                so = __shfl_xor_sync(0xffffffffu, s1, o);
                nm = fmaxf(m1, mo);
                s1 = s1 * __expf(m1 - nm) + so * __expf(mo - nm); m1 = nm;
            }
            if ((lane >> 2) == 0) {
                int cit = wn * 32 + jn * 8 + (lane & 3) * 2;
                SM_M[wm * 128 + cit]     = m0;  SM_S[wm * 128 + cit]     = s0;
                SM_M[wm * 128 + cit + 1] = m1;  SM_S[wm * 128 + cit + 1] = s1;
            }
        }
        __syncthreads();
        if (tid < 128) {
            float ma = SM_M[tid], mb = SM_M[128 + tid];
            float sa = SM_S[tid], sb = SM_S[128 + tid];
            float nm = fmaxf(ma, mb);
            float s = sa * __expf(ma - nm) + sb * __expf(mb - nm);
            g_pm[(size_t)blockIdx.y * cNK + col0 + tid] = nm;
            g_ps[(size_t)blockIdx.y * cNK + col0 + tid] = s;
        }
    }
}

// === 1-pass fp16 GEMM with fused softmax on A:
//     C = softmax(Sc) * B^T, where softmax(Sc)[i,k] = exp(Sc[i,k]-m[k])*rs[k].
//     A-tile: register-prefetched fp32 loads -> exp -> fp16 smem (2 stages ahead).
//     B-tile: cp.async 3-stage pipeline (unchanged). ===
static const int STAGE_B1 = 2 * TILE_B;        // A(fp16 post-exp), B
static const int SMEM_1P  = 3 * STAGE_B1;      // 61440
static const float LOG2E = 1.4426950408889634f;

__global__ __launch_bounds__(256, 1)
void mma_gemm_exp_f16(const float* __restrict__ Sc, const __half* __restrict__ B,
                      const float* __restrict__ gm, const float* __restrict__ grs,
                      float* __restrict__ C, int M, int N, int K)
{
    extern __shared__ char sm[];
    const uint32_t sbase = smem_to_u32(sm);

    const int tid = threadIdx.x;
    const int wid = tid >> 5, lane = tid & 31;
    const int wm = wid >> 2, wn = wid & 3;
    const int row0 = blockIdx.y * 128, col0 = blockIdx.x * 128;

    const float* Ab = Sc + (size_t)row0 * K;
    const __half* Bb = B + (size_t)col0 * K;

    const int NT = K >> 5;

    // A chunk mapping: 1024 chunks of 4 fp32; thread handles 4 (idx = tid + i*256)
    float4 ar[4];
    auto ldA = [&](int kt) {
        const int k0 = kt << 5;
#pragma unroll
        for (int i = 0; i < 4; ++i) {
            int idx = tid + i * 256;
            int row = idx >> 3, c = idx & 7;
            ar[i] = *(const float4*)(Ab + (size_t)row * K + k0 + c * 4);
        }
    };
    // exp + convert + store to fp16 smem tile (row*ROWB + k*2 layout)
    auto stA = [&](int kt, int s) {
        const int k0 = kt << 5;
#pragma unroll
        for (int i = 0; i < 4; ++i) {
            int idx = tid + i * 256;
            int row = idx >> 3, c = idx & 7;
            float4 m4 = *(const float4*)(gm + k0 + c * 4);
            float4 r4 = *(const float4*)(grs + k0 + c * 4);
            float e0 = __expf(ar[i].x - m4.x) * r4.x;
            float e1 = __expf(ar[i].y - m4.y) * r4.y;
            float e2 = __expf(ar[i].z - m4.z) * r4.z;
            float e3 = __expf(ar[i].w - m4.w) * r4.w;
            __half2* d = (__half2*)(sm + s * STAGE_B1 + row * ROWB + c * 8);
            d[0] = __floats2half2_rn(e0, e1);
            d[1] = __floats2half2_rn(e2, e3);
        }
    };
    auto ldB = [&](int kt, int s) {
        const int k0 = kt << 5;
#pragma unroll
        for (int i = 0; i < 2; ++i) {
            int q = tid + i * 256;
            int row = q >> 2, c = q & 3;
            cp_async16(sbase + s * STAGE_B1 + TILE_B + row * ROWB + c * 16,
                       Bb + (size_t)row * K + k0 + c * 8);
        }
    };

    // Prologue: stages 0 and 1 fully resident; stage-2 A in flight.
    ldA(0); stA(0, 0); ldB(0, 0); cp_commit();
    ldA(1); stA(1, 1); ldB(1, 1); cp_commit();
    if (NT > 2) ldA(2);

    float acc[4][4][4];
#pragma unroll
    for (int i = 0; i < 4; ++i)
#pragma unroll
        for (int j = 0; j < 4; ++j)
#pragma unroll
            for (int v = 0; v < 4; ++v) acc[i][j][v] = 0.f;

    const int lrow = lane & 15, lcol = lane >> 4;

    for (int kt = 0; kt < NT; ++kt) {
        const int s = kt % 3;
        cp_wait<1>();
        __syncthreads();
        if (kt + 2 < NT) {
            stA(kt + 2, (kt + 2) % 3);   // consumes ar loaded last iteration
            ldB(kt + 2, (kt + 2) % 3);
            if (kt + 3 < NT) ldA(kt + 3);
        }
        cp_commit();

#pragma unroll
        for (int ks = 0; ks < 2; ++ks) {
            uint32_t aa[4][4], bb[2][4];
            const uint32_t abase = sbase + s * STAGE_B1
                + (wm * 64 + lrow) * ROWB + ks * 32 + lcol * 16;
#pragma unroll
            for (int mi = 0; mi < 4; ++mi)
                ldsm_x4(aa[mi], abase + mi * 16 * ROWB);
            const uint32_t bbase = sbase + s * STAGE_B1 + TILE_B
                + (wn * 32 + lrow) * ROWB + ks * 32 + lcol * 16;
#pragma unroll
            for (int bj = 0; bj < 2; ++bj)
                ldsm_x4(bb[bj], bbase + bj * 16 * ROWB);
#pragma unroll
            for (int mi = 0; mi < 4; ++mi) {
#pragma unroll
                for (int jn = 0; jn < 4; ++jn) {
                    const int bj = jn >> 1, hf = jn & 1;
                    mma16816h(acc[mi][jn], aa[mi], bb[bj][hf], bb[bj][hf + 2]);
                }
            }
        }
    }

    const int g = lane >> 2, cq = (lane & 3) * 2;
#pragma unroll
    for (int mi = 0; mi < 4; ++mi) {
#pragma unroll
        for (int jn = 0; jn < 4; ++jn) {
            const int r0w = row0 + wm * 64 + mi * 16 + g;
            const int cc = col0 + wn * 32 + jn * 8 + cq;
            *(float2*)(C + (size_t)r0w * N + cc)
                = make_float2(acc[mi][jn][0], acc[mi][jn][1]);
            *(float2*)(C + (size_t)(r0w + 8) * N + cc)
                = make_float2(acc[mi][jn][2], acc[mi][jn][3]);
        }
    }
}

// ---------------------------------------------------------------------------
// Column softmax (axis 0): pass 1 fused into scores GEMM; pass 2 reduces
// chunk stats; fp32 attns output written off-critical-path (overlapped
// with the fused GEMM, which consumes raw scores + stats directly).
// ---------------------------------------------------------------------------
__global__ void softmax_pass2() {
    const int j = blockIdx.x * 256 + threadIdx.x;
    float m = -1e30f, s = 0.f;
#pragma unroll 8
    for (int c = 0; c < CHUNKS; ++c) {
        float pm = g_pm[(size_t)c * cNK + j];
        float ps = g_ps[(size_t)c * cNK + j];
        float nm = fmaxf(m, pm);
        s = s * __expf(m - nm) + ps * __expf(pm - nm);
        m = nm;
    }
    g_m[j] = m;
    g_rs[j] = 1.f / s;
}

// Read raw scores, write normalized fp32 attns to d_out (side stream).
__global__ void softmax_write_f32(const float* __restrict__ sc,
                                  float* __restrict__ out) {
    const int j4 = (blockIdx.x * 256 + threadIdx.x) * 4;
    const size_t i = blockIdx.y;
    float4 x = *(const float4*)(sc + i * cNK + j4);
    float4 m = *(const float4*)(&g_m[j4]);
    float4 rs = *(const float4*)(&g_rs[j4]);
    x.x = __expf(x.x - m.x) * rs.x;
    x.y = __expf(x.y - m.y) * rs.y;
    x.z = __expf(x.z - m.z) * rs.z;
    x.w = __expf(x.w - m.w) * rs.w;
    *(float4*)(out + i * cNK + j4) = x;
}

// ---------------------------------------------------------------------------
// Launch
// ---------------------------------------------------------------------------
extern "C" void kernel_launch(void* const* d_in, const int* in_sizes, int n_in,
                              void* d_out, int out_size)
{
    const float* Xs = (const float*)d_in[0];
    const float* Xk = (const float*)d_in[1];
    const float* Ws = (const float*)d_in[2];
    const float* bs = (const float*)d_in[3];
    const float* Wk = (const float*)d_in[4];
    const float* bk = (const float*)d_in[5];

    float* attns = (float*)d_out;
    float* fused = attns + (size_t)cNS * cNK;

    __nv_bfloat16 *Xsh, *Xsl, *Xkh, *Xkl, *Wsh, *Wsl, *Wkh, *Wkl;
    __nv_bfloat16 *Sh, *Sl, *Kh, *Kl;
    __half *VT;
    float *Scr, *Gm, *Grs;
    cudaGetSymbolAddress((void**)&Xsh, g_Xs_h); cudaGetSymbolAddress((void**)&Xsl, g_Xs_l);
    cudaGetSymbolAddress((void**)&Xkh, g_Xk_h); cudaGetSymbolAddress((void**)&Xkl, g_Xk_l);
    cudaGetSymbolAddress((void**)&Wsh, g_Ws_h); cudaGetSymbolAddress((void**)&Wsl, g_Ws_l);
    cudaGetSymbolAddress((void**)&Wkh, g_Wk_h); cudaGetSymbolAddress((void**)&Wkl, g_Wk_l);
    cudaGetSymbolAddress((void**)&Sh,  g_S_h);  cudaGetSymbolAddress((void**)&Sl,  g_S_l);
    cudaGetSymbolAddress((void**)&Kh,  g_K_h);  cudaGetSymbolAddress((void**)&Kl,  g_K_l);
    cudaGetSymbolAddress((void**)&VT,  g_VT);
    cudaGetSymbolAddress((void**)&Scr, g_Sc);
    cudaGetSymbolAddress((void**)&Gm,  g_m);
    cudaGetSymbolAddress((void**)&Grs, g_rs);

    cudaFuncSetAttribute(mma_gemm<true, true, false>,
                         cudaFuncAttributeMaxDynamicSharedMemorySize, SMEM_3P);
    cudaFuncSetAttribute(mma_gemm<false, false, true>,
                         cudaFuncAttributeMaxDynamicSharedMemorySize, SMEM_3P);
    cudaFuncSetAttribute(mma_gemm_exp_f16,
                         cudaFuncAttributeMaxDynamicSharedMemorySize, SMEM_1P);

    // Side stream + events (fork/join pattern proven graph-capture legal).
    static bool s_init = false;
    static bool s_ok = false;
    static cudaStream_t s_side;
    static cudaEvent_t evFork, evJoin, evFork2, evJoin2;
    if (!s_init) {
        s_init = true;
        s_ok = (cudaStreamCreateWithFlags(&s_side, cudaStreamNonBlocking) == cudaSuccess)
            && (cudaEventCreateWithFlags(&evFork,  cudaEventDisableTiming) == cudaSuccess)
            && (cudaEventCreateWithFlags(&evJoin,  cudaEventDisableTiming) == cudaSuccess)
            && (cudaEventCreateWithFlags(&evFork2, cudaEventDisableTiming) == cudaSuccess)
            && (cudaEventCreateWithFlags(&evJoin2, cudaEventDisableTiming) == cudaSuccess);
    }
    cudaStream_t sd = s_ok ? s_side : (cudaStream_t)0;

    // Main stream: Xs / Ws splits (feed S-projection)
    {
        size_t n;
        n = (size_t)cNS * cHID; split_kernel<<<(unsigned)(n / 1024), 256>>>(Xs, Xsh, Xsl, n);
        n = (size_t)cHID * cHID; split_kernel<<<(unsigned)(n / 1024), 256>>>(Ws, Wsh, Wsl, n);
    }

    // Side stream: Xk split + V^T (single read of Xk), Wk split, K-projection.
    if (s_ok) {
        cudaEventRecord(evFork, 0);
        cudaStreamWaitEvent(s_side, evFork, 0);
    }
    split_transpose_kernel<<<dim3(cKED / 32, cNK / 32), dim3(32, 8), 0, sd>>>(
        Xk, Xkh, Xkl, VT, cNK, cKED);
    {
        size_t n = (size_t)cHID * cKED;
        split_kernel<<<(unsigned)(n / 1024), 256, 0, sd>>>(Wk, Wkh, Wkl, n);
    }
    mma_gemm<true, true, false><<<dim3(cHID / 128, cNK / 128), 256, SMEM_3P, sd>>>(
        Xkh, Xkl, Wkh, Wkl, bk, nullptr, Kh, Kl, cNK, cHID, cKED);
    if (s_ok) cudaEventRecord(evJoin, s_side);

    // S = Xs @ Ws^T + bs  -> split planes  [8192, 1024]   (main stream)
    mma_gemm<true, true, false><<<dim3(cHID / 128, cNS / 128), 256, SMEM_3P>>>(
        Xsh, Xsl, Wsh, Wsl, bs, nullptr, Sh, Sl, cNS, cHID, cHID);

    if (s_ok) cudaStreamWaitEvent(0, evJoin, 0);

    // scores = S @ K^T -> raw fp32 into g_Sc scratch; epilogue emits softmax
    // chunk stats (pass 1 fused).  chunk == blockIdx.y (128 rows).
    mma_gemm<false, false, true><<<dim3(cNK / 128, cNS / 128), 256, SMEM_3P>>>(
        Sh, Sl, Kh, Kl, nullptr, Scr, nullptr, nullptr, cNS, cNK, cHID);

    // pass 2: global per-column stats (tiny)
    softmax_pass2<<<cNK / 256, 256>>>();

    // fp32 attns output: reads g_Sc, writes d_out — overlaps the fused GEMM
    // (disjoint buffers: fused GEMM reads g_Sc/VT, writes fused region).
    if (s_ok) {
        cudaEventRecord(evFork2, 0);
        cudaStreamWaitEvent(s_side, evFork2, 0);
        softmax_write_f32<<<dim3(cNK / 1024, cNS), 256, 0, s_side>>>(Scr, attns);
        cudaEventRecord(evJoin2, s_side);
    } else {
        softmax_write_f32<<<dim3(cNK / 1024, cNS), 256>>>(Scr, attns);
    }

    // fused = softmax(Sc) @ V: exp fused into the A-tile load, 1-pass fp16.
    mma_gemm_exp_f16<<<dim3(cKED / 128, cNS / 128), 256, SMEM_1P>>>(
        Scr, VT, Gm, Grs, fused, cNS, cKED, cNK);

    // Join side stream so the captured graph is well-formed.
    if (s_ok) cudaStreamWaitEvent(0, evJoin2, 0);
}

// round 14
// speedup vs baseline: 1.3210x; 1.3210x over previous
#include <cuda_runtime.h>
#include <cuda_bf16.h>
#include <cuda_fp16.h>
#include <stdint.h>

// ---------------------------------------------------------------------------
// Problem dims
// ---------------------------------------------------------------------------
static const int cNS  = 8192;
static const int cNK  = 8192;
static const int cHID = 1024;
static const int cKED = 2048;
static const int CHUNKS = 64;  // softmax row chunks = one 128-row CTA tile each

// ---------------------------------------------------------------------------
// Scratch (__device__ globals; allocation-free)
// ---------------------------------------------------------------------------
__device__ __nv_bfloat16 g_Xs_h[(size_t)cNS * cHID];
__device__ __nv_bfloat16 g_Xs_l[(size_t)cNS * cHID];
__device__ __nv_bfloat16 g_Xk_h[(size_t)cNK * cKED];
__device__ __nv_bfloat16 g_Xk_l[(size_t)cNK * cKED];
__device__ __nv_bfloat16 g_Ws_h[(size_t)cHID * cHID];
__device__ __nv_bfloat16 g_Ws_l[(size_t)cHID * cHID];
__device__ __nv_bfloat16 g_Wk_h[(size_t)cHID * cKED];
__device__ __nv_bfloat16 g_Wk_l[(size_t)cHID * cKED];
__device__ __half g_S_h[(size_t)cNS * cHID];           // S split planes (fp16)
__device__ __half g_S_l[(size_t)cNS * cHID];
__device__ __half g_K_h[(size_t)cNK * cHID];           // K split planes (fp16)
__device__ __half g_K_l[(size_t)cNK * cHID];
__device__ __half g_VT[(size_t)cKED * cNK];            // V^T fp16 [2048, 8192]
__device__ __half g_At[(size_t)cNS * cNK];             // attns fp16 (single plane)
__device__ float g_pm[(size_t)CHUNKS * cNK];
__device__ float g_ps[(size_t)CHUNKS * cNK];
__device__ float g_m[cNK];
__device__ float g_rs[cNK];

// ---------------------------------------------------------------------------
// Helpers
// ---------------------------------------------------------------------------
__device__ __forceinline__ uint32_t smem_to_u32(const void* p) {
    uint32_t a;
    asm("{ .reg .u64 t; cvta.to.shared.u64 t, %1; cvt.u32.u64 %0, t; }"
        : "=r"(a) : "l"(p));
    return a;
}

__device__ __forceinline__ void cp_async16(uint32_t smem_addr, const void* gptr) {
    asm volatile("cp.async.cg.shared.global [%0], [%1], 16;\n"
                 :: "r"(smem_addr), "l"(__cvta_generic_to_global(gptr)));
}
__device__ __forceinline__ void cp_commit() {
    asm volatile("cp.async.commit_group;\n" ::: "memory");
}
template <int N>
__device__ __forceinline__ void cp_wait() {
    asm volatile("cp.async.wait_group %0;\n" :: "n"(N) : "memory");
}

__device__ __forceinline__ void ldsm_x4(uint32_t (&r)[4], uint32_t addr) {
    asm volatile("ldmatrix.sync.aligned.m8n8.x4.shared.b16 {%0,%1,%2,%3}, [%4];\n"
                 : "=r"(r[0]), "=r"(r[1]), "=r"(r[2]), "=r"(r[3]) : "r"(addr));
}

// bf16 in, fp32 acc
__device__ __forceinline__ void mma16816(float (&c)[4], const uint32_t (&a)[4],
                                         uint32_t b0, uint32_t b1) {
    asm volatile(
        "mma.sync.aligned.m16n8k16.row.col.f32.bf16.bf16.f32 "
        "{%0,%1,%2,%3}, {%4,%5,%6,%7}, {%8,%9}, {%0,%1,%2,%3};\n"
        : "+f"(c[0]), "+f"(c[1]), "+f"(c[2]), "+f"(c[3])
        : "r"(a[0]), "r"(a[1]), "r"(a[2]), "r"(a[3]), "r"(b0), "r"(b1));
}

// fp16 in, fp32 acc
__device__ __forceinline__ void mma16816h(float (&c)[4], const uint32_t (&a)[4],
                                          uint32_t b0, uint32_t b1) {
    asm volatile(
        "mma.sync.aligned.m16n8k16.row.col.f32.f16.f16.f32 "
        "{%0,%1,%2,%3}, {%4,%5,%6,%7}, {%8,%9}, {%0,%1,%2,%3};\n"
        : "+f"(c[0]), "+f"(c[1]), "+f"(c[2]), "+f"(c[3])
        : "r"(a[0]), "r"(a[1]), "r"(a[2]), "r"(a[3]), "r"(b0), "r"(b1));
}

// fp16 in, fp16 acc (cross-term passes; measures whether f16-acc is 2x rate)
__device__ __forceinline__ void mma16816hacc(uint32_t (&c)[2], const uint32_t (&a)[4],
                                             uint32_t b0, uint32_t b1) {
    asm volatile(
        "mma.sync.aligned.m16n8k16.row.col.f16.f16.f16.f16 "
        "{%0,%1}, {%2,%3,%4,%5}, {%6,%7}, {%0,%1};\n"
        : "+r"(c[0]), "+r"(c[1])
        : "r"(a[0]), "r"(a[1]), "r"(a[2]), "r"(a[3]), "r"(b0), "r"(b1));
}

__device__ __forceinline__ void split1(float x, __nv_bfloat16& h, __nv_bfloat16& l) {
    h = __float2bfloat16(x);
    l = __float2bfloat16(x - __bfloat162float(h));
}
__device__ __forceinline__ void split1h(float x, __half& h, __half& l) {
    h = __float2half(x);
    l = __float2half(x - __half2float(h));
}

// ---------------------------------------------------------------------------
// Split / fused split+transpose preprocessing
// ---------------------------------------------------------------------------
__global__ void split_kernel(const float* __restrict__ in,
                             __nv_bfloat16* __restrict__ hi,
                             __nv_bfloat16* __restrict__ lo, size_t n) {
    size_t i = ((size_t)blockIdx.x * 256 + threadIdx.x) * 4;
    if (i >= n) return;
    float4 v = *(const float4*)(in + i);
    __nv_bfloat16 h0, h1, h2, h3, l0, l1, l2, l3;
    split1(v.x, h0, l0); split1(v.y, h1, l1);
    split1(v.z, h2, l2); split1(v.w, h3, l3);
    *(__nv_bfloat162*)(hi + i)     = __nv_bfloat162(h0, h1);
    *(__nv_bfloat162*)(hi + i + 2) = __nv_bfloat162(h2, h3);
    *(__nv_bfloat162*)(lo + i)     = __nv_bfloat162(l0, l1);
    *(__nv_bfloat162*)(lo + i + 2) = __nv_bfloat162(l2, l3);
}

// Read Xk once: emit bf16 hi/lo planes (row-major) + fp16 V^T (transposed).
__global__ void split_transpose_kernel(const float* __restrict__ in,
                                       __nv_bfloat16* __restrict__ hi,
                                       __nv_bfloat16* __restrict__ lo,
                                       __half* __restrict__ vt,
                                       int R, int C) {
    __shared__ float t[32][33];
    int c0 = blockIdx.x * 32, r0 = blockIdx.y * 32;
    int tx = threadIdx.x, ty = threadIdx.y;
#pragma unroll
    for (int j = 0; j < 4; ++j) {
        float v = in[(size_t)(r0 + ty + j * 8) * C + c0 + tx];
        t[ty + j * 8][tx] = v;
        __nv_bfloat16 h, l; split1(v, h, l);
        size_t off = (size_t)(r0 + ty + j * 8) * C + c0 + tx;
        hi[off] = h; lo[off] = l;
    }
    __syncthreads();
#pragma unroll
    for (int j = 0; j < 4; ++j)
        vt[(size_t)(c0 + ty + j * 8) * R + r0 + tx] = __float2half(t[tx][ty + j * 8]);
}

// ---------------------------------------------------------------------------
// Common GEMM geometry: 128x128 CTA tile, BK=32, 3-stage cp.async pipeline,
// 8 warps (2x4), warp tile 64x32, 80B-padded SMEM rows (conflict-free ldsm).
// ---------------------------------------------------------------------------
static const int ROWB    = 80;                 // 64B data + 16B pad
static const int TILE_B  = 128 * ROWB;         // 10240 B per plane-tile
static const int STAGE_B3 = 4 * TILE_B;        // Ah, Al, Bh, Bl
static const int SMEM_3P  = 3 * STAGE_B3;      // 122880

// === Projection GEMM (bf16 in, fp32 acc, 3 passes): C = (Ah+Al)(Bh+Bl)^T + b
//     SPLIT epilogue emits fp16 hi/lo planes (feeds the scores GEMM). ===
__global__ __launch_bounds__(256, 1)
void mma_gemm_proj(const __nv_bfloat16* __restrict__ Ah, const __nv_bfloat16* __restrict__ Al,
                   const __nv_bfloat16* __restrict__ Bh, const __nv_bfloat16* __restrict__ Bl,
                   const float* __restrict__ bias,
                   __half* __restrict__ Ch, __half* __restrict__ Cl,
                   int M, int N, int K)
{
    extern __shared__ char sm[];
    const uint32_t sbase = smem_to_u32(sm);

    const int tid = threadIdx.x;
    const int wid = tid >> 5, lane = tid & 31;
    const int wm = wid >> 2, wn = wid & 3;      // 2 x 4 warp grid
    const int row0 = blockIdx.y * 128, col0 = blockIdx.x * 128;

    const __nv_bfloat16* srcs[4] = {
        Ah + (size_t)row0 * K, Al + (size_t)row0 * K,
        Bh + (size_t)col0 * K, Bl + (size_t)col0 * K };

    const int NT = K >> 5;

    auto issue_loads = [&](int kt, int s) {
        const int k0 = kt << 5;
#pragma unroll
        for (int i = 0; i < 8; ++i) {
            int q = tid + i * 256;
            int t = q >> 9, idx = q & 511;
            int row = idx >> 2, c = idx & 3;
            const __nv_bfloat16* g = srcs[t] + (size_t)row * K + k0 + c * 8;
            uint32_t d = sbase + s * STAGE_B3 + t * TILE_B + row * ROWB + c * 16;
            cp_async16(d, g);
        }
    };

    issue_loads(0, 0); cp_commit();
    issue_loads(1, 1); cp_commit();

    float acc[4][4][4];
#pragma unroll
    for (int i = 0; i < 4; ++i)
#pragma unroll
        for (int j = 0; j < 4; ++j)
#pragma unroll
            for (int v = 0; v < 4; ++v) acc[i][j][v] = 0.f;

    const int lrow = lane & 15, lcol = lane >> 4;

    for (int kt = 0; kt < NT; ++kt) {
        const int s = kt % 3;
        cp_wait<1>();
        __syncthreads();
        if (kt + 2 < NT) issue_loads(kt + 2, (kt + 2) % 3);
        cp_commit();

#pragma unroll
        for (int ks = 0; ks < 2; ++ks) {
            uint32_t ah[4][4], al[4][4], bh[2][4], bl[2][4];
            const uint32_t abase = sbase + s * STAGE_B3
                + (wm * 64 + lrow) * ROWB + ks * 32 + lcol * 16;
#pragma unroll
            for (int mi = 0; mi < 4; ++mi) {
                ldsm_x4(ah[mi], abase + mi * 16 * ROWB);
                ldsm_x4(al[mi], abase + mi * 16 * ROWB + TILE_B);
            }
            const uint32_t bbase = sbase + s * STAGE_B3 + 2 * TILE_B
                + (wn * 32 + lrow) * ROWB + ks * 32 + lcol * 16;
#pragma unroll
            for (int bj = 0; bj < 2; ++bj) {
                ldsm_x4(bh[bj], bbase + bj * 16 * ROWB);
                ldsm_x4(bl[bj], bbase + bj * 16 * ROWB + TILE_B);
            }
#pragma unroll
            for (int mi = 0; mi < 4; ++mi) {
#pragma unroll
                for (int jn = 0; jn < 4; ++jn) {
                    const int bj = jn >> 1, hf = jn & 1;
                    mma16816(acc[mi][jn], ah[mi], bh[bj][hf], bh[bj][hf + 2]);
                    mma16816(acc[mi][jn], ah[mi], bl[bj][hf], bl[bj][hf + 2]);
                    mma16816(acc[mi][jn], al[mi], bh[bj][hf], bh[bj][hf + 2]);
                }
            }
        }
    }

    const int g = lane >> 2, cq = (lane & 3) * 2;
#pragma unroll
    for (int mi = 0; mi < 4; ++mi) {
#pragma unroll
        for (int jn = 0; jn < 4; ++jn) {
            const int r0w = row0 + wm * 64 + mi * 16 + g;
            const int cc = col0 + wn * 32 + jn * 8 + cq;
            float b0 = bias[cc], b1 = bias[cc + 1];
            float v0 = acc[mi][jn][0] + b0, v1 = acc[mi][jn][1] + b1;
            float v2 = acc[mi][jn][2] + b0, v3 = acc[mi][jn][3] + b1;
            __half h0, h1, h2, h3, l0, l1, l2, l3;
            split1h(v0, h0, l0); split1h(v1, h1, l1);
            split1h(v2, h2, l2); split1h(v3, h3, l3);
            size_t o0 = (size_t)r0w * N + cc;
            size_t o1 = (size_t)(r0w + 8) * N + cc;
            *(__half2*)(Ch + o0) = __halves2half2(h0, h1);
            *(__half2*)(Cl + o0) = __halves2half2(l0, l1);
            *(__half2*)(Ch + o1) = __halves2half2(h2, h3);
            *(__half2*)(Cl + o1) = __halves2half2(l2, l3);
        }
    }
}

// === Scores GEMM (fp16 in): hh pass fp32-acc; hl/lh cross passes fp16-acc.
//     Writes raw fp32 scores; STATS epilogue emits softmax chunk stats. ===
__global__ __launch_bounds__(256, 1)
void mma_gemm_scores(const __half* __restrict__ Ah, const __half* __restrict__ Al,
                     const __half* __restrict__ Bh, const __half* __restrict__ Bl,
                     float* __restrict__ C, int M, int N, int K)
{
    extern __shared__ char sm[];
    const uint32_t sbase = smem_to_u32(sm);

    const int tid = threadIdx.x;
    const int wid = tid >> 5, lane = tid & 31;
    const int wm = wid >> 2, wn = wid & 3;
    const int row0 = blockIdx.y * 128, col0 = blockIdx.x * 128;

    const __half* srcs[4] = {
        Ah + (size_t)row0 * K, Al + (size_t)row0 * K,
        Bh + (size_t)col0 * K, Bl + (size_t)col0 * K };

    const int NT = K >> 5;

    auto issue_loads = [&](int kt, int s) {
        const int k0 = kt << 5;
#pragma unroll
        for (int i = 0; i < 8; ++i) {
            int q = tid + i * 256;
            int t = q >> 9, idx = q & 511;
            int row = idx >> 2, c = idx & 3;
            const __half* g = srcs[t] + (size_t)row * K + k0 + c * 8;
            uint32_t d = sbase + s * STAGE_B3 + t * TILE_B + row * ROWB + c * 16;
            cp_async16(d, g);
        }
    };

    issue_loads(0, 0); cp_commit();
    issue_loads(1, 1); cp_commit();

    float acc[4][4][4];
    uint32_t acch[4][4][2];
#pragma unroll
    for (int i = 0; i < 4; ++i)
#pragma unroll
        for (int j = 0; j < 4; ++j) {
#pragma unroll
            for (int v = 0; v < 4; ++v) acc[i][j][v] = 0.f;
            acch[i][j][0] = 0u; acch[i][j][1] = 0u;
        }

    const int lrow = lane & 15, lcol = lane >> 4;

    for (int kt = 0; kt < NT; ++kt) {
        const int s = kt % 3;
        cp_wait<1>();
        __syncthreads();
        if (kt + 2 < NT) issue_loads(kt + 2, (kt + 2) % 3);
        cp_commit();

#pragma unroll
        for (int ks = 0; ks < 2; ++ks) {
            uint32_t ah[4][4], al[4][4], bh[2][4], bl[2][4];
            const uint32_t abase = sbase + s * STAGE_B3
                + (wm * 64 + lrow) * ROWB + ks * 32 + lcol * 16;
#pragma unroll
            for (int mi = 0; mi < 4; ++mi) {
                ldsm_x4(ah[mi], abase + mi * 16 * ROWB);
                ldsm_x4(al[mi], abase + mi * 16 * ROWB + TILE_B);
            }
            const uint32_t bbase = sbase + s * STAGE_B3 + 2 * TILE_B
                + (wn * 32 + lrow) * ROWB + ks * 32 + lcol * 16;
#pragma unroll
            for (int bj = 0; bj < 2; ++bj) {
                ldsm_x4(bh[bj], bbase + bj * 16 * ROWB);
                ldsm_x4(bl[bj], bbase + bj * 16 * ROWB + TILE_B);
            }
#pragma unroll
            for (int mi = 0; mi < 4; ++mi) {
#pragma unroll
                for (int jn = 0; jn < 4; ++jn) {
                    const int bj = jn >> 1, hf = jn & 1;
                    mma16816h(acc[mi][jn], ah[mi], bh[bj][hf], bh[bj][hf + 2]);
                    mma16816hacc(acch[mi][jn], ah[mi], bl[bj][hf], bl[bj][hf + 2]);
                    mma16816hacc(acch[mi][jn], al[mi], bh[bj][hf], bh[bj][hf + 2]);
                }
            }
        }
    }

    // Fold fp16 cross accumulators into the fp32 accumulators.
#pragma unroll
    for (int mi = 0; mi < 4; ++mi) {
#pragma unroll
        for (int jn = 0; jn < 4; ++jn) {
            float2 c01 = __half22float2(*reinterpret_cast<__half2*>(&acch[mi][jn][0]));
            float2 c23 = __half22float2(*reinterpret_cast<__half2*>(&acch[mi][jn][1]));
            acc[mi][jn][0] += c01.x; acc[mi][jn][1] += c01.y;
            acc[mi][jn][2] += c23.x; acc[mi][jn][3] += c23.y;
        }
    }

    const int g = lane >> 2, cq = (lane & 3) * 2;
#pragma unroll
    for (int mi = 0; mi < 4; ++mi) {
#pragma unroll
        for (int jn = 0; jn < 4; ++jn) {
            const int r0w = row0 + wm * 64 + mi * 16 + g;
            const int cc = col0 + wn * 32 + jn * 8 + cq;
            *(float2*)(C + (size_t)r0w * N + cc)
                = make_float2(acc[mi][jn][0], acc[mi][jn][1]);
            *(float2*)(C + (size_t)(r0w + 8) * N + cc)
                = make_float2(acc[mi][jn][2], acc[mi][jn][3]);
        }
    }

    // Softmax pass-1 from registers (per-column max/sumexp over 128 rows).
    cp_wait<0>();
    __syncthreads();
    float* SM_M = (float*)sm;            // [2][128]
    float* SM_S = (float*)(sm + 1024);   // [2][128]
#pragma unroll
    for (int jn = 0; jn < 4; ++jn) {
        float m0 = -1e30f, m1 = -1e30f;
#pragma unroll
        for (int mi = 0; mi < 4; ++mi) {
            m0 = fmaxf(m0, fmaxf(acc[mi][jn][0], acc[mi][jn][2]));
            m1 = fmaxf(m1, fmaxf(acc[mi][jn][1], acc[mi][jn][3]));
        }
        float s0 = 0.f, s1 = 0.f;
#pragma unroll
        for (int mi = 0; mi < 4; ++mi) {
            s0 += __expf(acc[mi][jn][0] - m0) + __expf(acc[mi][jn][2] - m0);
            s1 += __expf(acc[mi][jn][1] - m1) + __expf(acc[mi][jn][3] - m1);
        }
#pragma unroll
        for (int o = 4; o < 32; o <<= 1) {
            float mo = __shfl_xor_sync(0xffffffffu, m0, o);
            float so = __shfl_xor_sync(0xffffffffu, s0, o);
            float nm = fmaxf(m0, mo);
            s0 = s0 * __expf(m0 - nm) + so * __expf(mo - nm); m0 = nm;
            mo = __shfl_xor_sync(0xffffffffu, m1, o);
            so = __shfl_xor_sync(0xffffffffu, s1, o);
            nm = fmaxf(m1, mo);
            s1 = s1 * __expf(m1 - nm) + so * __expf(mo - nm); m1 = nm;
        }
        if ((lane >> 2) == 0) {
            int cit = wn * 32 + jn * 8 + (lane & 3) * 2;
            SM_M[wm * 128 + cit]     = m0;  SM_S[wm * 128 + cit]     = s0;
            SM_M[wm * 128 + cit + 1] = m1;  SM_S[wm * 128 + cit + 1] = s1;
        }
    }
    __syncthreads();
    if (tid < 128) {
        float ma = SM_M[tid], mb = SM_M[128 + tid];
        float sa = SM_S[tid], sb = SM_S[128 + tid];
        float nm = fmaxf(ma, mb);
        float s = sa * __expf(ma - nm) + sb * __expf(mb - nm);
        g_pm[(size_t)blockIdx.y * cNK + col0 + tid] = nm;
        g_ps[(size_t)blockIdx.y * cNK + col0 + tid] = s;
    }
}

// === 1-pass fp16 GEMM: C = A * B^T, fp32 accumulate (fused GEMM) ===
static const int STAGE_B1 = 2 * TILE_B;        // A, B
static const int SMEM_1P  = 3 * STAGE_B1;      // 61440

__global__ __launch_bounds__(256, 1)
void mma_gemm_f16(const __half* __restrict__ A, const __half* __restrict__ B,
                  float* __restrict__ C, int M, int N, int K)
{
    extern __shared__ char sm[];
    const uint32_t sbase = smem_to_u32(sm);

    const int tid = threadIdx.x;
    const int wid = tid >> 5, lane = tid & 31;
    const int wm = wid >> 2, wn = wid & 3;
    const int row0 = blockIdx.y * 128, col0 = blockIdx.x * 128;

    const __half* srcs[2] = { A + (size_t)row0 * K, B + (size_t)col0 * K };

    const int NT = K >> 5;

    auto issue_loads = [&](int kt, int s) {
        const int k0 = kt << 5;
#pragma unroll
        for (int i = 0; i < 4; ++i) {
            int q = tid + i * 256;
            int t = q >> 9, idx = q & 511;
            int row = idx >> 2, c = idx & 3;
            const __half* g = srcs[t] + (size_t)row * K + k0 + c * 8;
            uint32_t d = sbase + s * STAGE_B1 + t * TILE_B + row * ROWB + c * 16;
            cp_async16(d, g);
        }
    };

    issue_loads(0, 0); cp_commit();
    issue_loads(1, 1); cp_commit();

    float acc[4][4][4];
#pragma unroll
    for (int i = 0; i < 4; ++i)
#pragma unroll
        for (int j = 0; j < 4; ++j)
#pragma unroll
            for (int v = 0; v < 4; ++v) acc[i][j][v] = 0.f;

    const int lrow = lane & 15, lcol = lane >> 4;

    for (int kt = 0; kt < NT; ++kt) {
        const int s = kt % 3;
        cp_wait<1>();
        __syncthreads();
        if (kt + 2 < NT) issue_loads(kt + 2, (kt + 2) % 3);
        cp_commit();

#pragma unroll
        for (int ks = 0; ks < 2; ++ks) {
            uint32_t aa[4][4], bb[2][4];
            const uint32_t abase = sbase + s * STAGE_B1
                + (wm * 64 + lrow) * ROWB + ks * 32 + lcol * 16;
#pragma unroll
            for (int mi = 0; mi < 4; ++mi)
                ldsm_x4(aa[mi], abase + mi * 16 * ROWB);
            const uint32_t bbase = sbase + s * STAGE_B1 + TILE_B
                + (wn * 32 + lrow) * ROWB + ks * 32 + lcol * 16;
#pragma unroll
            for (int bj = 0; bj < 2; ++bj)
                ldsm_x4(bb[bj], bbase + bj * 16 * ROWB);
#pragma unroll
            for (int mi = 0; mi < 4; ++mi) {
#pragma unroll
                for (int jn = 0; jn < 4; ++jn) {
                    const int bj = jn >> 1, hf = jn & 1;
                    mma16816h(acc[mi][jn], aa[mi], bb[bj][hf], bb[bj][hf + 2]);
                }
            }
        }
    }

    const int g = lane >> 2, cq = (lane & 3) * 2;
#pragma unroll
    for (int mi = 0; mi < 4; ++mi) {
#pragma unroll
        for (int jn = 0; jn < 4; ++jn) {
            const int r0w = row0 + wm * 64 + mi * 16 + g;
            const int cc = col0 + wn * 32 + jn * 8 + cq;
            *(float2*)(C + (size_t)r0w * N + cc)
                = make_float2(acc[mi][jn][0], acc[mi][jn][1]);
            *(float2*)(C + (size_t)(r0w + 8) * N + cc)
                = make_float2(acc[mi][jn][2], acc[mi][jn][3]);
        }
    }
}

// ---------------------------------------------------------------------------
// Column softmax (axis 0): pass 1 fused into scores GEMM; pass 2 reduces
// chunk stats; pass 3 split: fp16 emit (critical path) + fp32 in-place
// normalize (overlapped with the fused GEMM on the side stream).
// ---------------------------------------------------------------------------
__global__ void softmax_pass2() {
    const int j = blockIdx.x * 256 + threadIdx.x;
    float m = -1e30f, s = 0.f;
#pragma unroll 8
    for (int c = 0; c < CHUNKS; ++c) {
        float pm = g_pm[(size_t)c * cNK + j];
        float ps = g_ps[(size_t)c * cNK + j];
        float nm = fmaxf(m, pm);
        s = s * __expf(m - nm) + ps * __expf(pm - nm);
        m = nm;
    }
    g_m[j] = m;
    g_rs[j] = 1.f / s;
}

__global__ void softmax_emit_f16(const float* __restrict__ sc,
                                 __half* __restrict__ at) {
    const int j4 = (blockIdx.x * 256 + threadIdx.x) * 4;
    const size_t i = blockIdx.y;
    float4 x = *(const float4*)(sc + i * cNK + j4);
    float4 m = *(const float4*)(&g_m[j4]);
    float4 rs = *(const float4*)(&g_rs[j4]);
    float e0 = __expf(x.x - m.x) * rs.x;
    float e1 = __expf(x.y - m.y) * rs.y;
    float e2 = __expf(x.z - m.z) * rs.z;
    float e3 = __expf(x.w - m.w) * rs.w;
    size_t off = i * cNK + j4;
    *(__half2*)(at + off)     = __floats2half2_rn(e0, e1);
    *(__half2*)(at + off + 2) = __floats2half2_rn(e2, e3);
}

__global__ void softmax_norm_f32(float* __restrict__ sc) {
    const int j4 = (blockIdx.x * 256 + threadIdx.x) * 4;
    const size_t i = blockIdx.y;
    float4 x = *(float4*)(sc + i * cNK + j4);
    float4 m = *(const float4*)(&g_m[j4]);
    float4 rs = *(const float4*)(&g_rs[j4]);
    x.x = __expf(x.x - m.x) * rs.x;
    x.y = __expf(x.y - m.y) * rs.y;
    x.z = __expf(x.z - m.z) * rs.z;
    x.w = __expf(x.w - m.w) * rs.w;
    *(float4*)(sc + i * cNK + j4) = x;
}

// ---------------------------------------------------------------------------
// Launch
// ---------------------------------------------------------------------------
extern "C" void kernel_launch(void* const* d_in, const int* in_sizes, int n_in,
                              void* d_out, int out_size)
{
    const float* Xs = (const float*)d_in[0];
    const float* Xk = (const float*)d_in[1];
    const float* Ws = (const float*)d_in[2];
    const float* bs = (const float*)d_in[3];
    const float* Wk = (const float*)d_in[4];
    const float* bk = (const float*)d_in[5];

    float* attns = (float*)d_out;
    float* fused = attns + (size_t)cNS * cNK;

    __nv_bfloat16 *Xsh, *Xsl, *Xkh, *Xkl, *Wsh, *Wsl, *Wkh, *Wkl;
    __half *Sh, *Sl, *Kh, *Kl, *VT, *At;
    cudaGetSymbolAddress((void**)&Xsh, g_Xs_h); cudaGetSymbolAddress((void**)&Xsl, g_Xs_l);
    cudaGetSymbolAddress((void**)&Xkh, g_Xk_h); cudaGetSymbolAddress((void**)&Xkl, g_Xk_l);
    cudaGetSymbolAddress((void**)&Wsh, g_Ws_h); cudaGetSymbolAddress((void**)&Wsl, g_Ws_l);
    cudaGetSymbolAddress((void**)&Wkh, g_Wk_h); cudaGetSymbolAddress((void**)&Wkl, g_Wk_l);
    cudaGetSymbolAddress((void**)&Sh,  g_S_h);  cudaGetSymbolAddress((void**)&Sl,  g_S_l);
    cudaGetSymbolAddress((void**)&Kh,  g_K_h);  cudaGetSymbolAddress((void**)&Kl,  g_K_l);
    cudaGetSymbolAddress((void**)&VT,  g_VT);
    cudaGetSymbolAddress((void**)&At,  g_At);

    cudaFuncSetAttribute(mma_gemm_proj,
                         cudaFuncAttributeMaxDynamicSharedMemorySize, SMEM_3P);
    cudaFuncSetAttribute(mma_gemm_scores,
                         cudaFuncAttributeMaxDynamicSharedMemorySize, SMEM_3P);
    cudaFuncSetAttribute(mma_gemm_f16,
                         cudaFuncAttributeMaxDynamicSharedMemorySize, SMEM_1P);

    // Side stream + events (fork/join pattern proven graph-capture legal).
    static bool s_init = false;
    static bool s_ok = false;
    static cudaStream_t s_side;
    static cudaEvent_t evFork, evJoin, evFork2, evJoin2;
    if (!s_init) {
        s_init = true;
        s_ok = (cudaStreamCreateWithFlags(&s_side, cudaStreamNonBlocking) == cudaSuccess)
            && (cudaEventCreateWithFlags(&evFork,  cudaEventDisableTiming) == cudaSuccess)
            && (cudaEventCreateWithFlags(&evJoin,  cudaEventDisableTiming) == cudaSuccess)
            && (cudaEventCreateWithFlags(&evFork2, cudaEventDisableTiming) == cudaSuccess)
            && (cudaEventCreateWithFlags(&evJoin2, cudaEventDisableTiming) == cudaSuccess);
    }
    cudaStream_t sd = s_ok ? s_side : (cudaStream_t)0;

    // Main stream: Xs / Ws splits (feed S-projection)
    {
        size_t n;
        n = (size_t)cNS * cHID; split_kernel<<<(unsigned)(n / 1024), 256>>>(Xs, Xsh, Xsl, n);
        n = (size_t)cHID * cHID; split_kernel<<<(unsigned)(n / 1024), 256>>>(Ws, Wsh, Wsl, n);
    }

    // Side stream: Xk split + V^T (single read of Xk), Wk split, K-projection.
    if (s_ok) {
        cudaEventRecord(evFork, 0);
        cudaStreamWaitEvent(s_side, evFork, 0);
    }
    split_transpose_kernel<<<dim3(cKED / 32, cNK / 32), dim3(32, 8), 0, sd>>>(
        Xk, Xkh, Xkl, VT, cNK, cKED);
    {
        size_t n = (size_t)cHID * cKED;
        split_kernel<<<(unsigned)(n / 1024), 256, 0, sd>>>(Wk, Wkh, Wkl, n);
    }
    mma_gemm_proj<<<dim3(cHID / 128, cNK / 128), 256, SMEM_3P, sd>>>(
        Xkh, Xkl, Wkh, Wkl, bk, Kh, Kl, cNK, cHID, cKED);
    if (s_ok) cudaEventRecord(evJoin, s_side);

    // S = Xs @ Ws^T + bs  -> fp16 split planes  [8192, 1024]  (main stream)
    mma_gemm_proj<<<dim3(cHID / 128, cNS / 128), 256, SMEM_3P>>>(
        Xsh, Xsl, Wsh, Wsl, bs, Sh, Sl, cNS, cHID, cHID);

    if (s_ok) cudaStreamWaitEvent(0, evJoin, 0);

    // scores = S @ K^T -> raw fp32 into attns region (d_out); epilogue emits
    // softmax chunk stats. hh pass fp32-acc, cross passes fp16-acc.
    mma_gemm_scores<<<dim3(cNK / 128, cNS / 128), 256, SMEM_3P>>>(
        Sh, Sl, Kh, Kl, attns, cNS, cNK, cHID);

    // pass 2 (global stats) + fp16 emit (critical path)
    softmax_pass2<<<cNK / 256, 256>>>();
    softmax_emit_f16<<<dim3(cNK / 1024, cNS), 256>>>(attns, At);

    // fp32 normalize in place, overlapped with the fused GEMM.
    if (s_ok) {
        cudaEventRecord(evFork2, 0);
        cudaStreamWaitEvent(s_side, evFork2, 0);
        softmax_norm_f32<<<dim3(cNK / 1024, cNS), 256, 0, s_side>>>(attns);
        cudaEventRecord(evJoin2, s_side);
    } else {
        softmax_norm_f32<<<dim3(cNK / 1024, cNS), 256>>>(attns);
    }

    // fused = attns @ V = At @ VT^T  [8192, 2048], 1-pass fp16  (main stream)
    mma_gemm_f16<<<dim3(cKED / 128, cNS / 128), 256, SMEM_1P>>>(
        At, VT, fused, cNS, cKED, cNK);

    // Join side stream so the captured graph is well-formed.
    if (s_ok) cudaStreamWaitEvent(0, evJoin2, 0);
}